// round 4
// baseline (speedup 1.0000x reference)
#include <cuda_runtime.h>
#include <cuda_bf16.h>

#define NL 51        // NUM_LABELS
#define LS 53        // LABEL_SIZE
#define LPAD 56      // padded to multiple of 4 for float4 shared loads
#define START_IDX 51
#define END_IDX 52

__global__ __launch_bounds__(64, 8)
void crf_fwd_kernel(const float* __restrict__ logits,
                    const int*   __restrict__ labels,
                    const int*   __restrict__ lens,
                    const float* __restrict__ transition,
                    float* __restrict__ out, int S)
{
    __shared__ float sh_T[LS * LS];
    __shared__ __align__(16) float sh_e[2][LPAD];
    __shared__ float sh_a[64];
    __shared__ float sh_red[64];
    __shared__ float sh_C;

    const int b = blockIdx.x;
    const int j = threadIdx.x;
    const int len = lens[b];

    // ---- load transition into shared (used for E, gold binary, final norm) ----
    for (int k = j; k < LS * LS; k += 64) sh_T[k] = transition[k];
    if (j < LPAD) { sh_e[0][j] = 0.f; sh_e[1][j] = 0.f; }
    __syncthreads();

    // ---- per-thread row of E = exp(T[j,:] - rowmax), kept in registers ----
    float Er[LPAD];
    float rmax = 0.f;
    if (j < LS) {
        rmax = -1e30f;
        #pragma unroll
        for (int i = 0; i < LS; i++) rmax = fmaxf(rmax, sh_T[j * LS + i]);
        #pragma unroll
        for (int i = 0; i < LS; i++) Er[i] = __expf(sh_T[j * LS + i] - rmax);
        #pragma unroll
        for (int i = LS; i < LPAD; i++) Er[i] = 0.f;
    } else {
        #pragma unroll
        for (int i = 0; i < LPAD; i++) Er[i] = 0.f;
    }

    // ---- gold score partials (unary + binary), parallel over t ----
    const float* Lb = logits + (size_t)b * S * NL;
    const int*   lab = labels + (size_t)b * S;
    {
        float g = 0.f;
        for (int t = j; t < len; t += 64) {
            int lt = lab[t];
            g += Lb[(size_t)t * NL + lt];
            int lp = (t == 0) ? START_IDX : lab[t - 1];
            g += sh_T[lt * LS + lp];
        }
        if (j == 0) g += sh_T[END_IDX * LS + lab[len - 1]];   // closing END transition
        sh_red[j] = g;
    }
    // (sh_red is read only after later barriers inside the scan loop)

    // ---- forward recurrence ----
    float a = (j < LS) ? ((j == START_IDX) ? 0.f : -100.f) : -1e30f;
    float C = 0.f;

    // distance-2 logit prefetch; rows 51/52 are the -100 padding of logits_p
    float lg_cur, lg_nxt;
    {
        int t0 = 0, t1 = (1 < S) ? 1 : 0;
        lg_cur = (j < NL) ? Lb[(size_t)t0 * NL + j] : -100.f;
        lg_nxt = (j < NL) ? Lb[(size_t)t1 * NL + j] : -100.f;
    }

    int buf = 0;
    for (int t = 0; t < len; t++) {
        float e = __expf(a - C);
        if (j < LPAD) sh_e[buf][j] = e;
        __syncthreads();

        // dot over i: 14 x float4 broadcast loads, 4 independent accumulators
        float s0 = 0.f, s1 = 0.f, s2 = 0.f, s3 = 0.f;
        const float4* p = (const float4*)sh_e[buf];
        #pragma unroll
        for (int q = 0; q < LPAD / 4; q++) {
            float4 v = p[q];
            s0 += v.x * Er[4 * q + 0];
            s1 += v.y * Er[4 * q + 1];
            s2 += v.z * Er[4 * q + 2];
            s3 += v.w * Er[4 * q + 3];
        }
        float s = (s0 + s1) + (s2 + s3);

        float lg = lg_cur;
        lg_cur = lg_nxt;
        {   // prefetch t+2 (clamped; unused when beyond len)
            int tt = t + 2; if (tt > S - 1) tt = S - 1;
            lg_nxt = (j < NL) ? Lb[(size_t)tt * NL + j] : -100.f;
        }

        a = lg + C + rmax + __logf(s);

        // renormalize offset every 4 steps
        if ((t & 3) == 3) {
            sh_a[j] = a;                // lanes >= LS hold -inf/-1e30: harmless
            __syncthreads();
            if (j < 32) {
                float m = fmaxf(sh_a[j], sh_a[j + 32]);
                m = fmaxf(m, __shfl_xor_sync(0xffffffffu, m, 16));
                m = fmaxf(m, __shfl_xor_sync(0xffffffffu, m, 8));
                m = fmaxf(m, __shfl_xor_sync(0xffffffffu, m, 4));
                m = fmaxf(m, __shfl_xor_sync(0xffffffffu, m, 2));
                m = fmaxf(m, __shfl_xor_sync(0xffffffffu, m, 1));
                if (j == 0) sh_C = m;
            }
            __syncthreads();
            C = sh_C;
        }
        buf ^= 1;
    }

    // ---- norm = logsumexp_j(alpha[j] + T[END, j]) ; combine and write ----
    sh_a[j] = (j < LS) ? (a + sh_T[END_IDX * LS + j]) : -1e30f;
    __syncthreads();
    if (j == 0) {
        float m = -1e30f;
        #pragma unroll
        for (int i = 0; i < LS; i++) m = fmaxf(m, sh_a[i]);
        float ssum = 0.f;
        #pragma unroll
        for (int i = 0; i < LS; i++) ssum += __expf(sh_a[i] - m);
        float norm = m + __logf(ssum);

        float gold = 0.f;
        #pragma unroll
        for (int i = 0; i < 64; i++) gold += sh_red[i];

        out[b] = gold - norm;
    }
}

extern "C" void kernel_launch(void* const* d_in, const int* in_sizes, int n_in,
                              void* d_out, int out_size)
{
    const float* logits     = (const float*)d_in[0];
    const int*   labels     = (const int*)  d_in[1];
    const int*   lens       = (const int*)  d_in[2];
    const float* transition = (const float*)d_in[3];
    float* out = (float*)d_out;

    int B = out_size;                 // 256
    int S = in_sizes[1] / B;          // labels is (B, S) -> 2048

    crf_fwd_kernel<<<B, 64>>>(logits, labels, lens, transition, out, S);
}